// round 2
// baseline (speedup 1.0000x reference)
#include <cuda_runtime.h>
#include <cstdint>

#define XDIM 1024
#define KDIM 64
#define IT 32
#define NCHUNK (XDIM / IT)
#define ROWS_PER_CTA 128
#define THREADS 256

// smem stage layout (floats)
#define XS_STRIDE 36                         // pad 4 -> float4-aligned rows, conflict-free
#define XS_FLOATS (ROWS_PER_CTA * XS_STRIDE) // 4608
#define VS_FLOATS (IT * KDIM)                // 2048 (natural layout, 256B per i)
#define WS_FLOATS IT                         // 32 (full-row w per i)
#define STAGE_FLOATS (XS_FLOATS + VS_FLOATS + WS_FLOATS)  // 6688
#define SMEM_BYTES (2 * STAGE_FLOATS * 4)    // 53504

__device__ float g_w[XDIM];   // w[i] = sum_k v[i][k]^2 (all 64 k)

__device__ __forceinline__ unsigned smaddr(const void* p) {
    return (unsigned)__cvta_generic_to_shared(p);
}
__device__ __forceinline__ void cp16(unsigned dst, const void* src) {
    asm volatile("cp.async.cg.shared.global [%0], [%1], 16;" :: "r"(dst), "l"(src));
}
__device__ __forceinline__ unsigned long long bcast2(float x) {
    unsigned long long r;
    asm("mov.b64 %0, {%1, %1};" : "=l"(r) : "f"(x));
    return r;
}
__device__ __forceinline__ unsigned long long pack2(float lo, float hi) {
    unsigned long long r;
    asm("mov.b64 %0, {%1, %2};" : "=l"(r) : "f"(lo), "f"(hi));
    return r;
}
__device__ __forceinline__ void fma2(unsigned long long& d, unsigned long long a,
                                     unsigned long long b) {
    asm volatile("fma.rn.f32x2 %0, %1, %2, %0;" : "+l"(d) : "l"(a), "l"(b));
}
__device__ __forceinline__ unsigned long long mul2(unsigned long long a,
                                                   unsigned long long b) {
    unsigned long long r;
    asm("mul.rn.f32x2 %0, %1, %2;" : "=l"(r) : "l"(a), "l"(b));
    return r;
}
__device__ __forceinline__ float lo2(unsigned long long v) {
    return __uint_as_float((unsigned)(v & 0xffffffffull));
}
__device__ __forceinline__ float hi2(unsigned long long v) {
    return __uint_as_float((unsigned)(v >> 32));
}

__global__ void prep_kernel(const float* __restrict__ v) {
    int i = blockIdx.x * blockDim.x + threadIdx.x;
    if (i < XDIM) {
        const float4* vr = (const float4*)(v + (size_t)i * KDIM);
        float s = 0.f;
        #pragma unroll
        for (int j = 0; j < 16; j++) {
            float4 a = vr[j];
            s = fmaf(a.x, a.x, s);
            s = fmaf(a.y, a.y, s);
            s = fmaf(a.z, a.z, s);
            s = fmaf(a.w, a.w, s);
        }
        g_w[i] = s;
    }
}

__global__ __launch_bounds__(THREADS, 1)
void fm_main(const float* __restrict__ x, const float* __restrict__ v,
             float* __restrict__ out) {
    extern __shared__ float smem[];
    const int tid = threadIdx.x;
    const int kq = tid & 3;            // k-quarter: k in [kq*16, kq*16+16)
    const int rg = tid >> 2;           // 0..63 -> rows 2rg, 2rg+1
    const int row0 = blockIdx.x * ROWS_PER_CTA;
    const int xorm = kq & 2;           // bank-conflict-avoidance chunk permutation

    unsigned long long a0[8], a1[8];   // 16 f32x2 accumulators = 32 y values
    #pragma unroll
    for (int j = 0; j < 8; j++) { a0[j] = 0ull; a1[j] = 0ull; }
    unsigned long long q0 = 0ull, q1 = 0ull;   // packed sum_of_square accumulators

    auto load_chunk = [&](int c, int s) {
        float* xs = smem + s * STAGE_FLOATS;
        float* vs = xs + XS_FLOATS;
        float* ws = vs + VS_FLOATS;
        const int i0 = c * IT;
        // x tile: 128 rows x 32 floats = 1024 float4 -> 4 cp16 per thread
        #pragma unroll
        for (int n = 0; n < 4; n++) {
            int g = tid + n * THREADS;        // float4 index
            int r = g >> 3, cc = g & 7;       // row, float4-col
            cp16(smaddr(xs + r * XS_STRIDE + cc * 4),
                 x + (size_t)(row0 + r) * XDIM + i0 + cc * 4);
        }
        // v tile: 32 i x 64 floats = 512 float4 -> 2 cp16 per thread (natural layout)
        #pragma unroll
        for (int n = 0; n < 2; n++) {
            int g = tid + n * THREADS;
            cp16(smaddr(vs) + g * 16, v + (size_t)i0 * KDIM + g * 4);
        }
        // w tile: 32 floats = 8 float4
        if (tid < 8) cp16(smaddr(ws) + tid * 16, g_w + i0 + tid * 4);
        asm volatile("cp.async.commit_group;");
    };

    auto compute_chunk = [&](int s) {
        const float* xs = smem + s * STAGE_FLOATS;
        const char* vb = (const char*)(xs + XS_FLOATS) + kq * 64;  // this quarter
        const float* ws = xs + XS_FLOATS + VS_FLOATS;
        const float* xr0 = xs + (2 * rg) * XS_STRIDE;
        const float* xr1 = xr0 + XS_STRIDE;
        #pragma unroll 2
        for (int ib = 0; ib < IT; ib += 4) {
            float4 xa = *(const float4*)(xr0 + ib);
            float4 xb = *(const float4*)(xr1 + ib);
            ulonglong2 wv = *(const ulonglong2*)(ws + ib);   // (w_i,w_i+1),(w_i+2,w_i+3)
            // sum_of_square, vectorized: q += x^2 * w (pairs)
            unsigned long long pa01 = pack2(xa.x, xa.y), pa23 = pack2(xa.z, xa.w);
            unsigned long long pb01 = pack2(xb.x, xb.y), pb23 = pack2(xb.z, xb.w);
            fma2(q0, mul2(pa01, pa01), wv.x);
            fma2(q0, mul2(pa23, pa23), wv.y);
            fma2(q1, mul2(pb01, pb01), wv.x);
            fma2(q1, mul2(pb23, pb23), wv.y);
            #pragma unroll
            for (int u = 0; u < 4; u++) {
                float x0 = (u == 0) ? xa.x : (u == 1) ? xa.y : (u == 2) ? xa.z : xa.w;
                float x1 = (u == 0) ? xb.x : (u == 1) ? xb.y : (u == 2) ? xb.z : xb.w;
                unsigned long long xx0 = bcast2(x0);
                unsigned long long xx1 = bcast2(x1);
                const char* vrow = vb + (ib + u) * 256;
                #pragma unroll
                for (int c = 0; c < 4; c++) {
                    ulonglong2 vv = *(const ulonglong2*)(vrow + ((c ^ xorm) * 16));
                    int j = 2 * (c ^ xorm);
                    fma2(a0[j],     vv.x, xx0);
                    fma2(a0[j + 1], vv.y, xx0);
                    fma2(a1[j],     vv.x, xx1);
                    fma2(a1[j + 1], vv.y, xx1);
                }
            }
        }
    };

    load_chunk(0, 0);
    for (int c = 0; c < NCHUNK; c++) {
        if (c + 1 < NCHUNK) {
            load_chunk(c + 1, (c + 1) & 1);
            asm volatile("cp.async.wait_group 1;");
        } else {
            asm volatile("cp.async.wait_group 0;");
        }
        __syncthreads();
        compute_chunk(c & 1);
        __syncthreads();
    }

    // epilogue: sum y^2 over this thread's 16 k's, reduce over 4 kq lanes
    float s0 = 0.f, s1 = 0.f;
    #pragma unroll
    for (int j = 0; j < 8; j++) {
        float lo = lo2(a0[j]), hi = hi2(a0[j]);
        s0 = fmaf(lo, lo, s0);
        s0 = fmaf(hi, hi, s0);
        lo = lo2(a1[j]); hi = hi2(a1[j]);
        s1 = fmaf(lo, lo, s1);
        s1 = fmaf(hi, hi, s1);
    }
    s0 += __shfl_xor_sync(0xffffffffu, s0, 1);
    s0 += __shfl_xor_sync(0xffffffffu, s0, 2);
    s1 += __shfl_xor_sync(0xffffffffu, s1, 1);
    s1 += __shfl_xor_sync(0xffffffffu, s1, 2);
    if (kq == 0) {
        // q computed with full-row w: identical in all 4 lanes, subtract once
        float qa = lo2(q0) + hi2(q0);
        float qb = lo2(q1) + hi2(q1);
        float2 r;
        r.x = 0.5f * (s0 - qa);
        r.y = 0.5f * (s1 - qb);
        *(float2*)(out + row0 + 2 * rg) = r;
    }
}

extern "C" void kernel_launch(void* const* d_in, const int* in_sizes, int n_in,
                              void* d_out, int out_size) {
    const float* x = (const float*)d_in[0];
    const float* v = (const float*)d_in[1];
    float* out = (float*)d_out;
    const int B = in_sizes[0] / XDIM;   // 16384

    prep_kernel<<<(XDIM + 127) / 128, 128>>>(v);

    cudaFuncSetAttribute(fm_main, cudaFuncAttributeMaxDynamicSharedMemorySize,
                         SMEM_BYTES);
    fm_main<<<B / ROWS_PER_CTA, THREADS, SMEM_BYTES>>>(x, v, out);
}

// round 3
// speedup vs baseline: 1.7768x; 1.7768x over previous
#include <cuda_runtime.h>
#include <cstdint>

#define XDIM 1024
#define KDIM 64
#define IT 32
#define NCHUNK (XDIM / IT)
#define ROWS_PER_CTA 128
#define THREADS 256

// smem stage layout (floats)
#define XS_STRIDE 33                         // pad 1 -> conflict-free scalar x LDS
#define XS_FLOATS (ROWS_PER_CTA * XS_STRIDE) // 4224
#define VS_ROWB 304                          // 4 quarters of 64B at +0,+80,+160,+240
#define VS_FLOATS (IT * (VS_ROWB / 4))       // 2432
#define WP_FLOATS (IT * 4)                   // 128 (quarter sums of v^2)
#define STAGE_FLOATS (XS_FLOATS + VS_FLOATS + WP_FLOATS)  // 6784
#define SMEM_BYTES (2 * STAGE_FLOATS * 4)    // 54272

__device__ float g_wp[XDIM * 4];   // wp[i][q] = sum_{k in q*16..q*16+16} v[i][k]^2

__device__ __forceinline__ unsigned smaddr(const void* p) {
    return (unsigned)__cvta_generic_to_shared(p);
}
__device__ __forceinline__ void cp4(unsigned dst, const void* src) {
    asm volatile("cp.async.ca.shared.global [%0], [%1], 4;" :: "r"(dst), "l"(src));
}
__device__ __forceinline__ void cp16(unsigned dst, const void* src) {
    asm volatile("cp.async.cg.shared.global [%0], [%1], 16;" :: "r"(dst), "l"(src));
}
__device__ __forceinline__ unsigned long long bcast2(float x) {
    unsigned long long r;
    asm("mov.b64 %0, {%1, %1};" : "=l"(r) : "f"(x));
    return r;
}
__device__ __forceinline__ void fma2(unsigned long long& d, unsigned long long a,
                                     unsigned long long b) {
    asm volatile("fma.rn.f32x2 %0, %1, %2, %0;" : "+l"(d) : "l"(a), "l"(b));
}
__device__ __forceinline__ float lo2(unsigned long long v) {
    return __uint_as_float((unsigned)(v & 0xffffffffull));
}
__device__ __forceinline__ float hi2(unsigned long long v) {
    return __uint_as_float((unsigned)(v >> 32));
}

__global__ void prep_kernel(const float* __restrict__ v) {
    int i = blockIdx.x * blockDim.x + threadIdx.x;
    if (i < XDIM) {
        #pragma unroll
        for (int q = 0; q < 4; q++) {
            float s = 0.f;
            #pragma unroll
            for (int k = 0; k < 16; k++) {
                float a = v[i * KDIM + q * 16 + k];
                s = fmaf(a, a, s);
            }
            g_wp[4 * i + q] = s;
        }
    }
}

__global__ __launch_bounds__(THREADS, 1)
void fm_main(const float* __restrict__ x, const float* __restrict__ v,
             float* __restrict__ out) {
    extern __shared__ float smem[];
    const int tid = threadIdx.x;
    const int kq = tid & 3;            // k-quarter: k in [kq*16, kq*16+16)
    const int rg = tid >> 2;           // 0..63 -> rows 2rg, 2rg+1
    const int row0 = blockIdx.x * ROWS_PER_CTA;

    unsigned long long a0[8], a1[8];   // 8 f32x2 per row = 16 y values per row
    #pragma unroll
    for (int j = 0; j < 8; j++) { a0[j] = 0ull; a1[j] = 0ull; }
    float q0 = 0.f, q1 = 0.f;          // per-quarter sum_of_square partials

    auto load_chunk = [&](int c, int s) {
        float* xs  = smem + s * STAGE_FLOATS;
        float* vs  = xs + XS_FLOATS;
        float* wps = vs + VS_FLOATS;
        const int i0 = c * IT;
        // x tile: 128 rows x 32 cols = 4096 words, 16 cp4 per thread
        #pragma unroll
        for (int n = 0; n < 16; n++) {
            int w = tid + n * THREADS;
            int r = w >> 5, col = w & 31;
            cp4(smaddr(xs + r * XS_STRIDE + col),
                x + (size_t)(row0 + r) * XDIM + i0 + col);
        }
        // v tile: 32 i-rows x 64 floats = 512 16B chunks, quarter-split layout
        #pragma unroll
        for (int n = 0; n < 2; n++) {
            int g = tid + n * THREADS;
            int i = g >> 4, rem = g & 15;
            int qq = rem >> 2, cc = rem & 3;
            cp16(smaddr(vs) + i * VS_ROWB + qq * 80 + cc * 16,
                 v + (size_t)(i0 + i) * KDIM + qq * 16 + cc * 4);
        }
        // wp tile: 128 floats = 32 chunks
        if (tid < 32) {
            cp16(smaddr(wps) + tid * 16, g_wp + i0 * 4 + tid * 4);
        }
        asm volatile("cp.async.commit_group;");
    };

    auto compute_chunk = [&](int s) {
        const float* xs  = smem + s * STAGE_FLOATS;
        const float* vs  = xs + XS_FLOATS;
        const float* wps = vs + VS_FLOATS;
        const float* xr0 = xs + (2 * rg) * XS_STRIDE;
        const float* xr1 = xr0 + XS_STRIDE;
        const char*  vb  = (const char*)vs + kq * 80;   // this thread's quarter
        #pragma unroll 4
        for (int i = 0; i < IT; i++) {
            float x0 = xr0[i], x1 = xr1[i];
            float wq = wps[i * 4 + kq];
            q0 = fmaf(x0 * x0, wq, q0);
            q1 = fmaf(x1 * x1, wq, q1);
            unsigned long long xx0 = bcast2(x0);
            unsigned long long xx1 = bcast2(x1);
            const ulonglong2* vp = (const ulonglong2*)(vb + i * VS_ROWB);
            #pragma unroll
            for (int j = 0; j < 4; j++) {
                ulonglong2 vv = vp[j];
                fma2(a0[2 * j + 0], vv.x, xx0);
                fma2(a0[2 * j + 1], vv.y, xx0);
                fma2(a1[2 * j + 0], vv.x, xx1);
                fma2(a1[2 * j + 1], vv.y, xx1);
            }
        }
    };

    load_chunk(0, 0);
    for (int c = 0; c < NCHUNK; c++) {
        if (c + 1 < NCHUNK) {
            load_chunk(c + 1, (c + 1) & 1);
            asm volatile("cp.async.wait_group 1;");
        } else {
            asm volatile("cp.async.wait_group 0;");
        }
        __syncthreads();
        compute_chunk(c & 1);
        __syncthreads();
    }

    // epilogue: sum y^2 over this thread's 16 k's, subtract per-quarter q,
    // then reduce across the 4 kq lanes (adjacent lanes 0..3)
    float s0 = 0.f, s1 = 0.f;
    #pragma unroll
    for (int j = 0; j < 8; j++) {
        float lo = lo2(a0[j]), hi = hi2(a0[j]);
        s0 = fmaf(lo, lo, s0);
        s0 = fmaf(hi, hi, s0);
        lo = lo2(a1[j]); hi = hi2(a1[j]);
        s1 = fmaf(lo, lo, s1);
        s1 = fmaf(hi, hi, s1);
    }
    float t0 = s0 - q0;
    float t1 = s1 - q1;
    t0 += __shfl_xor_sync(0xffffffffu, t0, 1);
    t0 += __shfl_xor_sync(0xffffffffu, t0, 2);
    t1 += __shfl_xor_sync(0xffffffffu, t1, 1);
    t1 += __shfl_xor_sync(0xffffffffu, t1, 2);
    if (kq == 0) {
        float2 r;
        r.x = 0.5f * t0;
        r.y = 0.5f * t1;
        *(float2*)(out + row0 + 2 * rg) = r;
    }
}

extern "C" void kernel_launch(void* const* d_in, const int* in_sizes, int n_in,
                              void* d_out, int out_size) {
    const float* x = (const float*)d_in[0];
    const float* v = (const float*)d_in[1];
    float* out = (float*)d_out;
    const int B = in_sizes[0] / XDIM;   // 16384

    prep_kernel<<<(XDIM + 127) / 128, 128>>>(v);

    cudaFuncSetAttribute(fm_main, cudaFuncAttributeMaxDynamicSharedMemorySize,
                         SMEM_BYTES);
    fm_main<<<B / ROWS_PER_CTA, THREADS, SMEM_BYTES>>>(x, v, out);
}